// round 16
// baseline (speedup 1.0000x reference)
#include <cuda_runtime.h>
#include <cuda_bf16.h>
#include <cstdint>
#include <cstddef>

// Problem constants
#define BT      16384
#define DMODEL  1024
#define NH      8
#define DHD     128
#define CHUNKL  64
#define NCHUNK  128
#define NBATCH  2
#define NCHTOT  2048
#define QSCALE  0.08838834764831843f
#define RMSEPS  1e-5f

// Scratch buffers
__device__ float g_kv[(size_t)NCHTOT * 16384];
__device__ __nv_bfloat16 g_ahi[(size_t)BT * DMODEL];
__device__ __nv_bfloat16 g_alo[(size_t)BT * DMODEL];
__device__ __nv_bfloat16 g_whi[(size_t)4 * DMODEL * DMODEL];   // qkv + o_w
__device__ __nv_bfloat16 g_wlo[(size_t)4 * DMODEL * DMODEL];
__device__ __nv_bfloat16 g_qhi[(size_t)BT * DMODEL];
__device__ __nv_bfloat16 g_qlo[(size_t)BT * DMODEL];
__device__ __nv_bfloat16 g_khi[(size_t)BT * DMODEL];
__device__ __nv_bfloat16 g_klo[(size_t)BT * DMODEL];
__device__ __nv_bfloat16 g_fwhi[4 * DHD * DHD];
__device__ __nv_bfloat16 g_fwlo[4 * DHD * DHD];
__device__ __nv_bfloat16 g_qnh[(size_t)BT * DMODEL];
__device__ __nv_bfloat16 g_qnl[(size_t)BT * DMODEL];
__device__ __nv_bfloat16 g_knh[(size_t)BT * DMODEL];
__device__ __nv_bfloat16 g_knl[(size_t)BT * DMODEL];
__device__ __nv_bfloat16 g_kth[(size_t)BT * DMODEL];
__device__ __nv_bfloat16 g_ktl[(size_t)BT * DMODEL];
__device__ __nv_bfloat16 g_vth[(size_t)BT * DMODEL];
__device__ __nv_bfloat16 g_vtl[(size_t)BT * DMODEL];
__device__ __nv_bfloat16 g_sh[(size_t)NCHTOT * 16384];
__device__ __nv_bfloat16 g_sl[(size_t)NCHTOT * 16384];

#define SWZ(off) ((off) ^ (((off) >> 3) & 0x70))

__device__ __forceinline__ uint32_t smem_u32(const void* p) {
    uint32_t a;
    asm("{ .reg .u64 t; cvta.to.shared.u64 t, %1; cvt.u32.u64 %0, t; }" : "=r"(a) : "l"(p));
    return a;
}

__device__ __forceinline__ void ldsm_x4(uint32_t addr, uint32_t& r0, uint32_t& r1,
                                        uint32_t& r2, uint32_t& r3) {
    asm volatile("ldmatrix.sync.aligned.m8n8.x4.shared.b16 {%0,%1,%2,%3}, [%4];"
                 : "=r"(r0), "=r"(r1), "=r"(r2), "=r"(r3) : "r"(addr));
}

__device__ __forceinline__ void mma_bf16(float* d, const uint32_t* a, const uint32_t* b) {
    asm volatile(
        "mma.sync.aligned.m16n8k16.row.col.f32.bf16.bf16.f32 "
        "{%0,%1,%2,%3}, {%4,%5,%6,%7}, {%8,%9}, {%0,%1,%2,%3};"
        : "+f"(d[0]), "+f"(d[1]), "+f"(d[2]), "+f"(d[3])
        : "r"(a[0]), "r"(a[1]), "r"(a[2]), "r"(a[3]), "r"(b[0]), "r"(b[1]));
}

__device__ __forceinline__ void cp_async16(uint32_t saddr, const void* gaddr) {
    asm volatile("cp.async.cg.shared.global [%0], [%1], 16;" :: "r"(saddr), "l"(gaddr));
}
#define CP_COMMIT() asm volatile("cp.async.commit_group;" ::: "memory")
#define CP_WAIT0()  asm volatile("cp.async.wait_group 0;" ::: "memory")
#define CP_WAIT1()  asm volatile("cp.async.wait_group 1;" ::: "memory")

__device__ __forceinline__ void split2(float a, float b, uint32_t& hi, uint32_t& lo) {
    __nv_bfloat16 ha = __float2bfloat16(a), hb = __float2bfloat16(b);
    __nv_bfloat16 la = __float2bfloat16(a - __bfloat162float(ha));
    __nv_bfloat16 lb = __float2bfloat16(b - __bfloat162float(hb));
    __nv_bfloat162 hp = __halves2bfloat162(ha, hb);
    __nv_bfloat162 lp = __halves2bfloat162(la, lb);
    hi = *(uint32_t*)&hp; lo = *(uint32_t*)&lp;
}

__device__ __forceinline__ void load_tile_async(uint32_t sdst, const void* gsrc,
                                                int slots, int tid) {
    for (int u = tid; u < slots; u += 256) {
        int row = u >> 3, cb = (u & 7) * 16;
        cp_async16(sdst + SWZ((uint32_t)(row * 128 + cb)),
                   (const char*)gsrc + (size_t)u * 16);
    }
}

// ---------------------------------------------------------------------------
// fp32 -> (hi, lo) bf16 split; 16 elems/thread, 4 independent load chains.
// ---------------------------------------------------------------------------
__device__ __forceinline__ void split16(const float* x, __nv_bfloat16* hi,
                                        __nv_bfloat16* lo, int i) {
    float4 v0 = *(const float4*)(x + i);
    float4 v1 = *(const float4*)(x + i + 4);
    float4 v2 = *(const float4*)(x + i + 8);
    float4 v3 = *(const float4*)(x + i + 12);
    uint32_t h[8], l[8];
    split2(v0.x, v0.y, h[0], l[0]);
    split2(v0.z, v0.w, h[1], l[1]);
    split2(v1.x, v1.y, h[2], l[2]);
    split2(v1.z, v1.w, h[3], l[3]);
    split2(v2.x, v2.y, h[4], l[4]);
    split2(v2.z, v2.w, h[5], l[5]);
    split2(v3.x, v3.y, h[6], l[6]);
    split2(v3.z, v3.w, h[7], l[7]);
    *(uint4*)(hi + i)     = make_uint4(h[0], h[1], h[2], h[3]);
    *(uint4*)(hi + i + 8) = make_uint4(h[4], h[5], h[6], h[7]);
    *(uint4*)(lo + i)     = make_uint4(l[0], l[1], l[2], l[3]);
    *(uint4*)(lo + i + 8) = make_uint4(l[4], l[5], l[6], l[7]);
}

__global__ void split_f32(const float* __restrict__ x, __nv_bfloat16* __restrict__ hi,
                          __nv_bfloat16* __restrict__ lo, int n) {
    int i = (blockIdx.x * blockDim.x + threadIdx.x) * 16;
    if (i >= n) return;
    split16(x, hi, lo, i);
}

__global__ void split_f32_b4(const float* x0, const float* x1,
                             const float* x2, const float* x3,
                             __nv_bfloat16* __restrict__ hi,
                             __nv_bfloat16* __restrict__ lo, int n) {
    int which = blockIdx.y;
    const float* x = (which == 0) ? x0 : (which == 1) ? x1 : (which == 2) ? x2 : x3;
    int i = (blockIdx.x * blockDim.x + threadIdx.x) * 16;
    if (i >= n || x == nullptr) return;
    split16(x, hi + (size_t)which * n, lo + (size_t)which * n, i);
}

// ---------------------------------------------------------------------------
// HMMA GEMM (R12 champion): 64x128 CTA tile, BK=64, 2-stage cp.async,
// 256 threads / 8 warps, warp tile 32x32. 97KB smem -> 2 CTAs/SM.
// ---------------------------------------------------------------------------
#define GEMM_STAGE   49152
#define GEMM_SMEM_BYTES (2 * GEMM_STAGE + 1024)
#define VT_ROW 80

__device__ __forceinline__ void gemm_load_stage(uint32_t sdst,
                                                const char* Ah, const char* Al,
                                                const char* Bh, const char* Bl,
                                                size_t kbyte, int tid) {
#pragma unroll
    for (int l = 0; l < 2; l++) {
        int u = tid + 256 * l;
        int row = u >> 3;
        int cb = (u & 7) * 16;
        uint32_t dsw = SWZ((uint32_t)(row * 128 + cb));
        size_t off = (size_t)row * 2048 + kbyte + cb;
        cp_async16(sdst + dsw,        Ah + off);
        cp_async16(sdst + 8192 + dsw, Al + off);
    }
#pragma unroll
    for (int l = 0; l < 4; l++) {
        int u = tid + 256 * l;
        int row = u >> 3;
        int cb = (u & 7) * 16;
        uint32_t dsw = SWZ((uint32_t)(row * 128 + cb));
        size_t off = (size_t)row * 2048 + kbyte + cb;
        cp_async16(sdst + 16384 + dsw, Bh + off);
        cp_async16(sdst + 32768 + dsw, Bl + off);
    }
}

__global__ __launch_bounds__(256) void gemm_mma2(
    const __nv_bfloat16* __restrict__ Ahi, const __nv_bfloat16* __restrict__ Alo,
    const __nv_bfloat16* __restrict__ Whi, const __nv_bfloat16* __restrict__ Wlo,
    __nv_bfloat16* __restrict__ Qhi, __nv_bfloat16* __restrict__ Qlo,
    __nv_bfloat16* __restrict__ Khi, __nv_bfloat16* __restrict__ Klo,
    __nv_bfloat16* __restrict__ VTh, __nv_bfloat16* __restrict__ VTl,
    float* __restrict__ Cout, int mode) {
    extern __shared__ char dynraw[];
    char* smem = (char*)(((uintptr_t)dynraw + 1023) & ~(uintptr_t)1023);
    const uint32_t sbase = smem_u32(smem);

    const int tid = threadIdx.x;
    const int wid = tid >> 5;
    const int lane = tid & 31;
    const int n0 = blockIdx.x * 128;
    const int m0 = blockIdx.y * 64;
    const int wm = (wid & 1) * 32;
    const int wn = (wid >> 1) * 32;

    float acc[2][4][4];
#pragma unroll
    for (int i = 0; i < 2; i++)
#pragma unroll
        for (int j = 0; j < 4; j++)
#pragma unroll
            for (int r = 0; r < 4; r++) acc[i][j][r] = 0.f;

    const char* srcA_h = (const char*)(Ahi + (size_t)m0 * 1024);
    const char* srcA_l = (const char*)(Alo + (size_t)m0 * 1024);
    const char* srcB_h = (const char*)(Whi + (size_t)n0 * 1024);
    const char* srcB_l = (const char*)(Wlo + (size_t)n0 * 1024);

    const int mat = lane >> 3;
    const int mrow = lane & 7;

    gemm_load_stage(sbase, srcA_h, srcA_l, srcB_h, srcB_l, 0, tid);
    CP_COMMIT();

    for (int kt = 0; kt < 16; kt++) {
        CP_WAIT0();
        __syncthreads();

        if (kt + 1 < 16) {
            gemm_load_stage(sbase + (uint32_t)((kt + 1) & 1) * GEMM_STAGE,
                            srcA_h, srcA_l, srcB_h, srcB_l,
                            (size_t)(kt + 1) * 128, tid);
            CP_COMMIT();
        }
        const uint32_t scur = sbase + (uint32_t)(kt & 1) * GEMM_STAGE;
        const uint32_t sAh = scur;
        const uint32_t sAl = scur + 8192;
        const uint32_t sBh = scur + 16384;
        const uint32_t sBl = scur + 32768;

#pragma unroll
        for (int kc = 0; kc < 4; kc++) {
            const int kb0 = kc * 32;
            uint32_t ah[2][4], al[2][4];
#pragma unroll
            for (int i = 0; i < 2; i++) {
                int arow = wm + i * 16 + (mat & 1) * 8 + mrow;
                int akb = kb0 + (mat >> 1) * 16;
                uint32_t off = SWZ((uint32_t)(arow * 128 + akb));
                ldsm_x4(sAh + off, ah[i][0], ah[i][1], ah[i][2], ah[i][3]);
                ldsm_x4(sAl + off, al[i][0], al[i][1], al[i][2], al[i][3]);
            }
#pragma unroll
            for (int p = 0; p < 2; p++) {
                int brow = wn + p * 16 + (mat >> 1) * 8 + mrow;
                int bkb = kb0 + (mat & 1) * 16;
                uint32_t off = SWZ((uint32_t)(brow * 128 + bkb));
                uint32_t bh[4], bl[4];
                ldsm_x4(sBh + off, bh[0], bh[1], bh[2], bh[3]);
                ldsm_x4(sBl + off, bl[0], bl[1], bl[2], bl[3]);
#pragma unroll
                for (int i = 0; i < 2; i++) {
                    mma_bf16(acc[i][2 * p],     ah[i], &bh[0]);
                    mma_bf16(acc[i][2 * p],     al[i], &bh[0]);
                    mma_bf16(acc[i][2 * p],     ah[i], &bl[0]);
                    mma_bf16(acc[i][2 * p + 1], ah[i], &bh[2]);
                    mma_bf16(acc[i][2 * p + 1], al[i], &bh[2]);
                    mma_bf16(acc[i][2 * p + 1], ah[i], &bl[2]);
                }
            }
        }
    }

    const int crow = lane >> 2;
    const int ccol = (lane & 3) * 2;
    if (mode == 1) {
#pragma unroll
        for (int i = 0; i < 2; i++) {
            int m = m0 + wm + i * 16 + crow;
#pragma unroll
            for (int j = 0; j < 4; j++) {
                int n = n0 + wn + j * 8 + ccol;
                *(float2*)(Cout + (size_t)m * 1024 + n) = make_float2(acc[i][j][0], acc[i][j][1]);
                *(float2*)(Cout + (size_t)(m + 8) * 1024 + n) = make_float2(acc[i][j][2], acc[i][j][3]);
            }
        }
        return;
    }
    int buf = n0 >> 10;
    int ncol0 = n0 & 1023;
    if (buf == 2) {
        __syncthreads();
        __nv_bfloat16* sVh = (__nv_bfloat16*)smem;
        __nv_bfloat16* sVl = (__nv_bfloat16*)(smem + 128 * VT_ROW * 2);
#pragma unroll
        for (int i = 0; i < 2; i++) {
            int ma = wm + i * 16 + crow;
            int mb = ma + 8;
#pragma unroll
            for (int j = 0; j < 4; j++) {
                int n = wn + j * 8 + ccol;
                uint32_t hi, lo;
                split2(acc[i][j][0], acc[i][j][1], hi, lo);
                __nv_bfloat162 hp = *(__nv_bfloat162*)&hi;
                __nv_bfloat162 lp = *(__nv_bfloat162*)&lo;
                sVh[n * VT_ROW + ma] = hp.x; sVh[(n + 1) * VT_ROW + ma] = hp.y;
                sVl[n * VT_ROW + ma] = lp.x; sVl[(n + 1) * VT_ROW + ma] = lp.y;
                split2(acc[i][j][2], acc[i][j][3], hi, lo);
                hp = *(__nv_bfloat162*)&hi;
                lp = *(__nv_bfloat162*)&lo;
                sVh[n * VT_ROW + mb] = hp.x; sVh[(n + 1) * VT_ROW + mb] = hp.y;
                sVl[n * VT_ROW + mb] = lp.x; sVl[(n + 1) * VT_ROW + mb] = lp.y;
            }
        }
        __syncthreads();
        const size_t cid = ((size_t)(m0 >> 13) * 8 + (ncol0 >> 7)) * 128 + ((m0 >> 6) & 127);
#pragma unroll
        for (int l = 0; l < 4; l++) {
            int u = tid + 256 * l;
            int dv = u >> 3;
            int t0 = (u & 7) * 8;
            size_t g = (cid << 13) + (size_t)dv * 64 + t0;
            *(uint4*)(VTh + g) = *(uint4*)(sVh + dv * VT_ROW + t0);
            *(uint4*)(VTl + g) = *(uint4*)(sVl + dv * VT_ROW + t0);
        }
    } else {
        __nv_bfloat16* H = buf ? Khi : Qhi;
        __nv_bfloat16* L = buf ? Klo : Qlo;
#pragma unroll
        for (int i = 0; i < 2; i++) {
            int m = m0 + wm + i * 16 + crow;
#pragma unroll
            for (int j = 0; j < 4; j++) {
                int n = ncol0 + wn + j * 8 + ccol;
                uint32_t hi, lo;
                split2(acc[i][j][0], acc[i][j][1], hi, lo);
                *(uint32_t*)(H + (size_t)m * 1024 + n) = hi;
                *(uint32_t*)(L + (size_t)m * 1024 + n) = lo;
                split2(acc[i][j][2], acc[i][j][3], hi, lo);
                *(uint32_t*)(H + (size_t)(m + 8) * 1024 + n) = hi;
                *(uint32_t*)(L + (size_t)(m + 8) * 1024 + n) = lo;
            }
        }
    }
}

// ---------------------------------------------------------------------------
// Feature map via HMMA, 64-token CTA tile, 2 CTAs/SM. Merged q/k launch.
// ---------------------------------------------------------------------------
#define FM_SMEM (98304 + 1024)

__global__ __launch_bounds__(256) void featmap_mma(
    const __nv_bfloat16* __restrict__ Qhi, const __nv_bfloat16* __restrict__ Qlo,
    const __nv_bfloat16* __restrict__ Khi, const __nv_bfloat16* __restrict__ Klo,
    const __nv_bfloat16* __restrict__ FWh, const __nv_bfloat16* __restrict__ FWl,
    const float* __restrict__ QB1, const float* __restrict__ QB2,
    const float* __restrict__ KB1, const float* __restrict__ KB2,
    __nv_bfloat16* __restrict__ QNh, __nv_bfloat16* __restrict__ QNl,
    __nv_bfloat16* __restrict__ KNh, __nv_bfloat16* __restrict__ KNl,
    __nv_bfloat16* __restrict__ OTh, __nv_bfloat16* __restrict__ OTl) {
    extern __shared__ char dynraw[];
    char* smem = (char*)(((uintptr_t)dynraw + 1023) & ~(uintptr_t)1023);
    const uint32_t sbase = smem_u32(smem);

    const int tid = threadIdx.x;
    const int wid = tid >> 5;
    const int lane = tid & 31;
    const int t0 = blockIdx.x * 64;
    const int h = blockIdx.y;
    const int isK = (int)(blockIdx.z >> 1);
    const int z = blockIdx.z & 1;
    const int wm = (wid & 1) * 32;
    const int wn = (wid >> 1) * 16;

    const int nF = DHD * DHD;
    const __nv_bfloat16* Xhi = isK ? Khi : Qhi;
    const __nv_bfloat16* Xlo = isK ? Klo : Qlo;
    const __nv_bfloat16* W1h = FWh + (isK ? 2 * nF : 0);
    const __nv_bfloat16* W1l = FWl + (isK ? 2 * nF : 0);
    const __nv_bfloat16* W2h = FWh + (isK ? 3 * nF : nF);
    const __nv_bfloat16* W2l = FWl + (isK ? 3 * nF : nF);
    const float* B1 = isK ? KB1 : QB1;
    const float* B2 = isK ? KB2 : QB2;
    __nv_bfloat16* ONh = isK ? KNh : QNh;
    __nv_bfloat16* ONl = isK ? KNl : QNl;
    const float scale = isK ? 1.0f : QSCALE;

    const __nv_bfloat16* wsel[4] = {W1h, W1l, W2h, W2l};

#pragma unroll
    for (int t = 0; t < 4; t++) {
        int half = t >> 1, hl = t & 1;
        const char* sp = (const char*)((hl ? Xlo : Xhi) +
                          (size_t)t0 * 1024 + h * 128 + half * 64);
#pragma unroll
        for (int l = 0; l < 2; l++) {
            int s = tid + 256 * l;
            int row = s >> 3, cb = (s & 7) * 16;
            cp_async16(sbase + t * 8192 + SWZ((uint32_t)(row * 128 + cb)),
                       sp + (size_t)row * 2048 + cb);
        }
    }
#pragma unroll
    for (int t = 0; t < 8; t++) {
        int half = t >> 2, wsub = (t >> 1) & 1, hl = t & 1;
        const char* sp = (const char*)wsel[wsub * 2 + hl] +
                         ((size_t)(z * 64) * 128 + half * 64) * 2;
#pragma unroll
        for (int l = 0; l < 2; l++) {
            int s = tid + 256 * l;
            int row = s >> 3, cb = (s & 7) * 16;
            cp_async16(sbase + 32768 + t * 8192 + SWZ((uint32_t)(row * 128 + cb)),
                       sp + (size_t)row * 256 + cb);
        }
    }
    CP_COMMIT();
    CP_WAIT0();
    __syncthreads();

    float acc1[2][2][4], acc2[2][2][4];
#pragma unroll
    for (int i = 0; i < 2; i++)
#pragma unroll
        for (int j = 0; j < 2; j++)
#pragma unroll
            for (int r = 0; r < 4; r++) { acc1[i][j][r] = 0.f; acc2[i][j][r] = 0.f; }

    const int mat = lane >> 3;
    const int mrow = lane & 7;

#pragma unroll
    for (int half = 0; half < 2; half++) {
        const uint32_t sXh = sbase + (half * 2 + 0) * 8192;
        const uint32_t sXl = sbase + (half * 2 + 1) * 8192;
        const uint32_t sW1h = sbase + 32768 + (half * 4 + 0) * 8192;
        const uint32_t sW1l = sbase + 32768 + (half * 4 + 1) * 8192;
        const uint32_t sW2h = sbase + 32768 + (half * 4 + 2) * 8192;
        const uint32_t sW2l = sbase + 32768 + (half * 4 + 3) * 8192;
#pragma unroll
        for (int kc = 0; kc < 4; kc++) {
            const int kb0 = kc * 32;
            uint32_t ah[2][4], al[2][4];
#pragma unroll
            for (int i = 0; i < 2; i++) {
                int arow = wm + i * 16 + (mat & 1) * 8 + mrow;
                int akb = kb0 + (mat >> 1) * 16;
                uint32_t off = SWZ((uint32_t)(arow * 128 + akb));
                ldsm_x4(sXh + off, ah[i][0], ah[i][1], ah[i][2], ah[i][3]);
                ldsm_x4(sXl + off, al[i][0], al[i][1], al[i][2], al[i][3]);
            }
            int brow = wn + (mat >> 1) * 8 + mrow;
            int bkb = kb0 + (mat & 1) * 16;
            uint32_t off = SWZ((uint32_t)(brow * 128 + bkb));
            uint32_t b1h[4], b1l[4], b2h[4], b2l[4];
            ldsm_x4(sW1h + off, b1h[0], b1h[1], b1h[2], b1h[3]);
            ldsm_x4(sW1l + off, b1l[0], b1l[1], b1l[2], b1l[3]);
            ldsm_x4(sW2h + off, b2h[0], b2h[1], b2h[2], b2h[3]);
            ldsm_x4(sW2l + off, b2l[0], b2l[1], b2l[2], b2l[3]);
#pragma unroll
            for (int i = 0; i < 2; i++) {
                mma_bf16(acc1[i][0], ah[i], &b1h[0]);
                mma_bf16(acc1[i][0], al[i], &b1h[0]);
                mma_bf16(acc1[i][0], ah[i], &b1l[0]);
                mma_bf16(acc1[i][1], ah[i], &b1h[2]);
                mma_bf16(acc1[i][1], al[i], &b1h[2]);
                mma_bf16(acc1[i][1], ah[i], &b1l[2]);
                mma_bf16(acc2[i][0], ah[i], &b2h[0]);
                mma_bf16(acc2[i][0], al[i], &b2h[0]);
                mma_bf16(acc2[i][0], ah[i], &b2l[0]);
                mma_bf16(acc2[i][1], ah[i], &b2h[2]);
                mma_bf16(acc2[i][1], al[i], &b2h[2]);
                mma_bf16(acc2[i][1], ah[i], &b2l[2]);
            }
        }
    }

    const int crow = lane >> 2;
    const int ccol = (lane & 3) * 2;
#pragma unroll
    for (int j = 0; j < 2; j++) {
        int d64 = wn + j * 8 + ccol;
        int nl = z * 64 + d64;
        float b1a = B1[nl], b1b = B1[nl + 1];
        float b2a = B2[nl], b2b = B2[nl + 1];
#pragma unroll
        for (int i = 0; i < 2; i++) {
#pragma unroll
            for (int rv = 0; rv < 2; rv++) {
                int m = t0 + wm + i * 16 + crow + rv * 8;
                float p0 = (acc1[i][j][rv * 2 + 0] + b1a) * (acc2[i][j][rv * 2 + 0] + b2a) * scale;
                float p1 = (acc1[i][j][rv * 2 + 1] + b1b) * (acc2[i][j][rv * 2 + 1] + b2b) * scale;
                uint32_t hi, lo;
                split2(p0, p1, hi, lo);
                int bb = m >> 13, nn = (m >> 6) & 127, cc = m & 63;
                size_t cidx = (size_t)(bb * 8 + h) * 128 + nn;
                size_t addrN = ((cidx * 2 + z) << 12) + cc * 64 + d64;
                *(uint32_t*)(ONh + addrN) = hi;
                *(uint32_t*)(ONl + addrN) = lo;
                if (isK) {
                    size_t addrT = (cidx << 13) + (size_t)nl * 64 + cc;
                    __nv_bfloat162 hp = *(__nv_bfloat162*)&hi;
                    __nv_bfloat162 lp = *(__nv_bfloat162*)&lo;
                    OTh[addrT] = hp.x; OTh[addrT + 64] = hp.y;
                    OTl[addrT] = lp.x; OTl[addrT + 64] = lp.y;
                }
            }
        }
    }
}

// ---------------------------------------------------------------------------
#define CKV_SMEM (65536 + 1024)

__global__ __launch_bounds__(256) void chunk_kv_mma(
    const __nv_bfloat16* __restrict__ VTh, const __nv_bfloat16* __restrict__ VTl,
    const __nv_bfloat16* __restrict__ KTh, const __nv_bfloat16* __restrict__ KTl,
    float* __restrict__ KV) {
    extern __shared__ char dynraw[];
    char* smem = (char*)(((uintptr_t)dynraw + 1023) & ~(uintptr_t)1023);
    const uint32_t sbase = smem_u32(smem);
    const int tid = threadIdx.x;
    const int wid = tid >> 5;
    const int lane = tid & 31;
    const size_t cid = blockIdx.x;
    const int wm = (wid & 3) * 32;
    const int wn = (wid >> 2) * 64;

    load_tile_async(sbase + 0,     VTh + (cid << 13), 1024, tid);
    load_tile_async(sbase + 16384, VTl + (cid << 13), 1024, tid);
    load_tile_async(sbase + 32768, KTh + (cid << 13), 1024, tid);
    load_tile_async(sbase + 49152, KTl + (cid << 13), 1024, tid);
    CP_COMMIT();
    CP_WAIT0();
    __syncthreads();

    float acc[2][8][4];
#pragma unroll
    for (int i = 0; i < 2; i++)
#pragma unroll
        for (int j = 0; j < 8; j++)
#pragma unroll
            for (int r = 0; r < 4; r++) acc[i][j][r] = 0.f;

    const int mat = lane >> 3;
    const int mrow = lane & 7;

#pragma unroll
    for (int kc = 0; kc < 4; kc++) {
        const int kb0 = kc * 32;
        uint32_t ah[2][4], al[2][4];
#pragma unroll
        for (int i = 0; i < 2; i++) {
            int arow = wm + i * 16 + (mat & 1) * 8 + mrow;
            int akb = kb0 + (mat >> 1) * 16;
            uint32_t off = SWZ((uint32_t)(arow * 128 + akb));
            ldsm_x4(sbase + off,         ah[i][0], ah[i][1], ah[i][2], ah[i][3]);
            ldsm_x4(sbase + 16384 + off, al[i][0], al[i][1], al[i][2], al[i][3]);
        }
#pragma unroll
        for (int p = 0; p < 4; p++) {
            int brow = wn + p * 16 + (mat >> 1) * 8 + mrow;
            int bkb = kb0 + (mat & 1) * 16;
            uint32_t off = SWZ((uint32_t)(brow * 128 + bkb));
            uint32_t bh[4], bl[4];
            ldsm_x4(sbase + 32768 + off, bh[0], bh[1], bh[2], bh[3]);
            ldsm_x4(sbase + 49152 + off, bl[0], bl[1], bl[2], bl[3]);
#pragma unroll
            for (int i = 0; i < 2; i++) {
                mma_bf16(acc[i][2 * p],     ah[i], &bh[0]);
                mma_bf16(acc[i][2 * p],     al[i], &bh[0]);
                mma_bf16(acc[i][2 * p],     ah[i], &bl[0]);
                mma_bf16(acc[i][2 * p + 1], ah[i], &bh[2]);
                mma_bf16(acc[i][2 * p + 1], al[i], &bh[2]);
                mma_bf16(acc[i][2 * p + 1], ah[i], &bl[2]);
            }
        }
    }

    const int crow = lane >> 2;
    const int ccol = (lane & 3) * 2;
    const int hk = wn >> 6;
#pragma unroll
    for (int i = 0; i < 2; i++) {
#pragma unroll
        for (int rv = 0; rv < 2; rv++) {
            int dv = wm + i * 16 + crow + rv * 8;
#pragma unroll
            for (int j = 0; j < 8; j++) {
                int dk64 = (wn & 63) + j * 8 + ccol;
                size_t addr = (cid << 14) + hk * 8192 + (size_t)dv * 64 + dk64;
                *(float2*)(KV + addr) = make_float2(acc[i][j][rv * 2], acc[i][j][rv * 2 + 1]);
            }
        }
    }
}

// ---------------------------------------------------------------------------
// exclusive cumsum over chunks, unrolled x8 for MLP, bf16 split output
// ---------------------------------------------------------------------------
__global__ void cumsum_split(const float* __restrict__ KV,
                             __nv_bfloat16* __restrict__ Sh,
                             __nv_bfloat16* __restrict__ Sl) {
    int bh = blockIdx.x;
    size_t i = blockIdx.y * 256 + threadIdx.x;
    size_t base = ((size_t)bh * 128 << 14) + i;
    float acc = 0.f;
#pragma unroll 1
    for (int n = 0; n < NCHUNK; n += 8) {
        size_t i0 = base + ((size_t)n << 14);
        float v[8];
#pragma unroll
        for (int u = 0; u < 8; u++)
            v[u] = KV[i0 + ((size_t)u << 14)];
#pragma unroll
        for (int u = 0; u < 8; u++) {
            size_t idx = i0 + ((size_t)u << 14);
            __nv_bfloat16 h = __float2bfloat16(acc);
            Sh[idx] = h;
            Sl[idx] = __float2bfloat16(acc - __bfloat162float(h));
            acc += v[u];
        }
    }
}

// ---------------------------------------------------------------------------
// chunk attention + fused RMSNorm + bf16 split (R12 champion, 256 threads)
// ---------------------------------------------------------------------------
#define CA_SMEM (180224 + 1024)

__global__ __launch_bounds__(256) void chunk_attn_mma(
    const __nv_bfloat16* __restrict__ QNh, const __nv_bfloat16* __restrict__ QNl,
    const __nv_bfloat16* __restrict__ KNh, const __nv_bfloat16* __restrict__ KNl,
    const __nv_bfloat16* __restrict__ VTh, const __nv_bfloat16* __restrict__ VTl,
    const __nv_bfloat16* __restrict__ Sh,  const __nv_bfloat16* __restrict__ Sl,
    const float* __restrict__ RW,
    __nv_bfloat16* __restrict__ Ohi, __nv_bfloat16* __restrict__ Olo) {
    extern __shared__ char dynraw[];
    char* smem = (char*)(((uintptr_t)dynraw + 1023) & ~(uintptr_t)1023);
    const uint32_t sQh = smem_u32(smem);
    const uint32_t sQl = sQh + 16384;
    const uint32_t sKh = sQh + 32768;
    const uint32_t sKl = sQh + 49152;
    const uint32_t sVh = sQh + 65536;
    const uint32_t sVl = sQh + 81920;
    const uint32_t sSh = sQh + 98304;
    const uint32_t sSl = sQh + 131072;
    const uint32_t sAh = sQh + 163840;
    const uint32_t sAl = sQh + 172032;
    __shared__ float ssbuf[64];

    const int tid = threadIdx.x;
    const int wid = tid >> 5;
    const int lane = tid & 31;
    const size_t cid = blockIdx.x;
    const int n = cid & 127;
    const int h = (cid >> 7) & 7;
    const int b = (int)(cid >> 10);

    load_tile_async(sQh, QNh + (cid << 13), 1024, tid);
    load_tile_async(sQl, QNl + (cid << 13), 1024, tid);
    load_tile_async(sKh, KNh + (cid << 13), 1024, tid);
    load_tile_async(sKl, KNl + (cid << 13), 1024, tid);
    CP_COMMIT();
    load_tile_async(sVh, VTh + (cid << 13), 1024, tid);
    load_tile_async(sVl, VTl + (cid << 13), 1024, tid);
    load_tile_async(sSh, Sh + (cid << 14), 2048, tid);
    load_tile_async(sSl, Sl + (cid << 14), 2048, tid);
    CP_COMMIT();
    CP_WAIT1();
    __syncthreads();

    const int mat = lane >> 3;
    const int mrow = lane & 7;
    const int crow = lane >> 2;
    const int ccol = (lane & 3) * 2;

    // ---- Step 1: A = Q K^T
    {
        const int wm1 = (wid & 1) * 32;
        const int wn1 = (wid >> 1) * 16;
        float acc[2][2][4];
#pragma unroll
        for (int i = 0; i < 2; i++)
#pragma unroll
            for (int j = 0; j < 2; j++)
#pragma unroll
                for (int r = 0; r < 4; r++) acc[i][j][r] = 0.f;

#pragma unroll
        for (int kc = 0; kc < 8; kc++) {
            int rbase = (kc >> 2) * 64;
            int kb0 = (kc & 3) * 32;
            uint32_t ah[2][4], al[2][4];
#pragma unroll
            for (int i = 0; i < 2; i++) {
                int arow = rbase + wm1 + i * 16 + (mat & 1) * 8 + mrow;
                int akb = kb0 + (mat >> 1) * 16;
                uint32_t off = SWZ((uint32_t)(arow * 128 + akb));
                ldsm_x4(sQh + off, ah[i][0], ah[i][1], ah[i][2], ah[i][3]);
                ldsm_x4(sQl + off, al[i][0], al[i][1], al[i][2], al[i][3]);
            }
            int brow = rbase + wn1 + (mat >> 1) * 8 + mrow;
            int bkb = kb0 + (mat & 1) * 16;
            uint32_t off = SWZ((uint32_t)(brow * 128 + bkb));
            uint32_t bh[4], bl[4];
            ldsm_x4(sKh + off, bh[0], bh[1], bh[2], bh[3]);
            ldsm_x4(sKl + off, bl[0], bl[1], bl[2], bl[3]);
#pragma unroll
            for (int i = 0; i < 2; i++) {
                mma_bf16(acc[i][0], ah[i], &bh[0]);
                mma_bf16(acc[i][0], al[i], &bh[0]);
                mma_bf16(acc[i][0], ah[i], &bl[0]);
                mma_bf16(acc[i][1], ah[i], &bh[2]);
                mma_bf16(acc[i][1], al[i], &bh[2]);
                mma_bf16(acc[i][1], ah[i], &bl[2]);
            }
        }
#pragma unroll
        for (int i = 0; i < 2; i++) {
#pragma unroll
            for (int rv = 0; rv < 2; rv++) {
                int c = wm1 + i * 16 + crow + rv * 8;
#pragma unroll
                for (int j = 0; j < 2; j++) {
                    int s = wn1 + j * 8 + ccol;
                    float v0 = (s <= c)     ? acc[i][j][rv * 2 + 0] : 0.f;
                    float v1 = (s + 1 <= c) ? acc[i][j][rv * 2 + 1] : 0.f;
                    uint32_t hi, lo;
                    split2(v0, v1, hi, lo);
                    uint32_t off = SWZ((uint32_t)(c * 128 + s * 2));
                    asm volatile("st.shared.b32 [%0], %1;" :: "r"(sAh + off), "r"(hi));
                    asm volatile("st.shared.b32 [%0], %1;" :: "r"(sAl + off), "r"(lo));
                }
            }
        }
    }
    if (tid < 64) ssbuf[tid] = 0.f;
    CP_WAIT0();
    __syncthreads();

    // ---- Step 2: O = A V + Q S
    const int wm2 = (wid & 1) * 32;
    const int wn2 = (wid >> 1) * 32;
    float acc[2][4][4];
#pragma unroll
    for (int i = 0; i < 2; i++)
#pragma unroll
        for (int j = 0; j < 4; j++)
#pragma unroll
            for (int r = 0; r < 4; r++) acc[i][j][r] = 0.f;

#pragma unroll
    for (int kc = 0; kc < 4; kc++) {
        int kb0 = kc * 32;
        uint32_t ah[2][4], al[2][4];
#pragma unroll
        for (int i = 0; i < 2; i++) {
            int arow = wm2 + i * 16 + (mat & 1) * 8 + mrow;
            int akb = kb0 + (mat >> 1) * 16;
            uint32_t off = SWZ((uint32_t)(arow * 128 + akb));
            ldsm_x4(sAh + off, ah[i][0], ah[i][1], ah[i][2], ah[i][3]);
            ldsm_x4(sAl + off, al[i][0], al[i][1], al[i][2], al[i][3]);
        }
#pragma unroll
        for (int p = 0; p < 2; p++) {
            int brow = wn2 + p * 16 + (mat >> 1) * 8 + mrow;
            int bkb = kb0 + (mat & 1) * 16;
            uint32_t off = SWZ((uint32_t)(brow * 128 + bkb));
            uint32_t bh[4], bl[4];
            ldsm_x4(sVh + off, bh[0], bh[1], bh[2], bh[3]);
            ldsm_x4(sVl + off, bl[0], bl[1], bl[2], bl[3]);
#pragma unroll
            for (int i = 0; i < 2; i++) {
                mma_bf16(acc[i][2 * p],     ah[i], &bh[0]);
                mma_bf16(acc[i][2 * p],     al[i], &bh[0]);
                mma_bf16(acc[i][2 * p],     ah[i], &bl[0]);
                mma_bf16(acc[i][2 * p + 1], ah[i], &bh[2]);
                mma_bf16(acc[i][2 * p + 1], al[i], &bh[2]);
                mma_bf16(acc[i][2 * p + 1], ah[i], &bl[2]);
            }
        }
    }
#pragma unroll
    for (int kc = 0; kc < 8; kc++) {
        int qrbase = (kc >> 2) * 64;
        int srbase = (kc >> 2) * 128;
        int kb0 = (kc & 3) * 32;
        uint32_t ah[2][4], al[2][4];
#pragma unroll
        for (int i = 0; i < 2; i++) {
            int arow = qrbase + wm2 + i * 16 + (mat & 1) * 8 + mrow;
            int akb = kb0 + (mat >> 1) * 16;
            uint32_t off = SWZ((uint32_t)(arow * 128 + akb));
            ldsm_x4(sQh + off, ah[i][0], ah[i][1], ah[i][2], ah[i][3]);
            ldsm_x4(sQl + off, al[i][0], al[i][1], al[i][2], al[i][3]);
        }
#pragma unroll
        for (int p = 0; p < 2; p++) {
            int brow = srbase + wn2 + p * 16 + (mat >> 1) * 8 + mrow;
            int bkb = kb0 + (mat & 1) * 16;
            uint32_t off = SWZ((uint32_t)(brow * 128 + bkb));
            uint32_t bh[4], bl[4];
            ldsm_x4(sSh + off, bh[0], bh[1], bh[2], bh[3]);
            ldsm_x4(sSl + off, bl[0], bl[1], bl[2], bl[3]);
#pragma unroll
            for (int i = 0; i < 2; i++) {
                mma_bf16(acc[i][2 * p],     ah[i], &bh[0]);
                mma_bf16(acc[i][2 * p],     al[i], &bh[0]);
                mma_bf16(acc[i][2 * p],     ah[i], &bl[0]);
                mma_bf16(acc[i][2 * p + 1], ah[i], &bh[2]);
                mma_bf16(acc[i][2 * p + 1], al[i], &bh[2]);
                mma_bf16(acc[i][2 * p + 1], ah[i], &bl[2]);
            }
        }
    }

    // Fused RMSNorm
#pragma unroll
    for (int i = 0; i < 2; i++) {
#pragma unroll
        for (int rv = 0; rv < 2; rv++) {
            float ss = 0.f;
#pragma unroll
            for (int j = 0; j < 4; j++) {
                float v0 = acc[i][j][rv * 2], v1 = acc[i][j][rv * 2 + 1];
                ss += v0 * v0 + v1 * v1;
            }
            ss += __shfl_xor_sync(0xffffffffu, ss, 1);
            ss += __shfl_xor_sync(0xffffffffu, ss, 2);
            if ((lane & 3) == 0)
                atomicAdd(&ssbuf[wm2 + i * 16 + crow + rv * 8], ss);
        }
    }
    __syncthreads();

    const size_t tbase = (size_t)b * 8192 + (size_t)n * 64;
#pragma unroll
    for (int i = 0; i < 2; i++) {
#pragma unroll
        for (int rv = 0; rv < 2; rv++) {
            int tl = wm2 + i * 16 + crow + rv * 8;
            float r = rsqrtf(ssbuf[tl] * (1.0f / 128.0f) + RMSEPS);
            size_t t = tbase + tl;
#pragma unroll
            for (int j = 0; j < 4; j++) {
                int dv = wn2 + j * 8 + ccol;
                float2 w = *(const float2*)(RW + dv);
                uint32_t hi, lo;
                split2(acc[i][j][rv * 2] * r * w.x, acc[i][j][rv * 2 + 1] * r * w.y, hi, lo);
                *(uint32_t*)(Ohi + t * 1024 + h * 128 + dv) = hi;
                *(uint32_t*)(Olo + t * 1024 + h * 128 + dv) = lo;
            }
        }
    }
}

// ---------------------------------------------------------------------------
extern "C" void kernel_launch(void* const* d_in, const int* in_sizes, int n_in,
                              void* d_out, int out_size) {
    const float* hidden = (const float*)d_in[0];
    const float* q_w    = (const float*)d_in[2];
    const float* k_w    = (const float*)d_in[3];
    const float* v_w    = (const float*)d_in[4];
    const float* o_w    = (const float*)d_in[5];
    const float* fmq_w1 = (const float*)d_in[6];
    const float* fmq_b1 = (const float*)d_in[7];
    const float* fmq_w2 = (const float*)d_in[8];
    const float* fmq_b2 = (const float*)d_in[9];
    const float* fmk_w1 = (const float*)d_in[10];
    const float* fmk_b1 = (const float*)d_in[11];
    const float* fmk_w2 = (const float*)d_in[12];
    const float* fmk_b2 = (const float*)d_in[13];
    const float* rms_w  = (const float*)d_in[14];
    float* out = (float*)d_out;

    float* kv;
    __nv_bfloat16 *ahi, *alo, *whi, *wlo, *qhi, *qlo, *khi, *klo, *fwhi, *fwlo;
    __nv_bfloat16 *qnh, *qnl, *knh, *knl, *kth, *ktl, *vth, *vtl, *sh, *sl;
    cudaGetSymbolAddress((void**)&kv,   g_kv);
    cudaGetSymbolAddress((void**)&ahi,  g_ahi);
    cudaGetSymbolAddress((void**)&alo,  g_alo);
    cudaGetSymbolAddress((void**)&whi,  g_whi);
    cudaGetSymbolAddress((void**)&wlo,  g_wlo);
    cudaGetSymbolAddress((void**)&qhi,  g_qhi);
    cudaGetSymbolAddress((void**)&qlo,  g_qlo);
    cudaGetSymbolAddress((void**)&khi,  g_khi);
    cudaGetSymbolAddress((void**)&klo,  g_klo);
    cudaGetSymbolAddress((void**)&fwhi, g_fwhi);
    cudaGetSymbolAddress((void**)&fwlo, g_fwlo);
    cudaGetSymbolAddress((void**)&qnh,  g_qnh);
    cudaGetSymbolAddress((void**)&qnl,  g_qnl);
    cudaGetSymbolAddress((void**)&knh,  g_knh);
    cudaGetSymbolAddress((void**)&knl,  g_knl);
    cudaGetSymbolAddress((void**)&kth,  g_kth);
    cudaGetSymbolAddress((void**)&ktl,  g_ktl);
    cudaGetSymbolAddress((void**)&vth,  g_vth);
    cudaGetSymbolAddress((void**)&vtl,  g_vtl);
    cudaGetSymbolAddress((void**)&sh,   g_sh);
    cudaGetSymbolAddress((void**)&sl,   g_sl);

    cudaFuncSetAttribute(gemm_mma2, cudaFuncAttributeMaxDynamicSharedMemorySize, GEMM_SMEM_BYTES);
    cudaFuncSetAttribute(featmap_mma, cudaFuncAttributeMaxDynamicSharedMemorySize, FM_SMEM);
    cudaFuncSetAttribute(chunk_kv_mma, cudaFuncAttributeMaxDynamicSharedMemorySize, CKV_SMEM);
    cudaFuncSetAttribute(chunk_attn_mma, cudaFuncAttributeMaxDynamicSharedMemorySize, CA_SMEM);

    const int nA = BT * DMODEL;
    const int nW = DMODEL * DMODEL;
    const int nF = DHD * DHD;

    // Splits (16 elems/thread): hidden; qkv+o weights batched; featmap weights
    split_f32<<<nA / 4096, 256>>>(hidden, ahi, alo, nA);
    split_f32_b4<<<dim3(nW / 4096, 4), 256>>>(q_w, k_w, v_w, o_w, whi, wlo, nW);
    split_f32_b4<<<dim3(nF / 4096, 4), 256>>>(fmq_w1, fmq_w2, fmk_w1, fmk_w2,
                                              fwhi, fwlo, nF);

    // QKV projection (64x128 tiles, 2 CTAs/SM)
    gemm_mma2<<<dim3(24, 256), 256, GEMM_SMEM_BYTES>>>(
        ahi, alo, whi, wlo, qhi, qlo, khi, klo, vth, vtl, nullptr, 0);

    // Feature maps: single merged launch (z: 0,1 -> q halves; 2,3 -> k halves)
    featmap_mma<<<dim3(BT / 64, NH, 4), 256, FM_SMEM>>>(
        qhi, qlo, khi, klo, fwhi, fwlo,
        fmq_b1, fmq_b2, fmk_b1, fmk_b2,
        qnh, qnl, knh, knl, kth, ktl);

    // Chunked linear attention (chunk_attn fuses RMSNorm + split -> ahi/alo)
    chunk_kv_mma<<<NCHTOT, 256, CKV_SMEM>>>(vth, vtl, kth, ktl, kv);
    cumsum_split<<<dim3(NBATCH * NH, 64), 256>>>(kv, sh, sl);
    chunk_attn_mma<<<NCHTOT, 256, CA_SMEM>>>(qnh, qnl, knh, knl, vth, vtl, sh, sl,
                                             rms_w, ahi, alo);

    // Output projection (o_w split already done; weights at slot 3)
    gemm_mma2<<<dim3(8, 256), 256, GEMM_SMEM_BYTES>>>(
        ahi, alo, whi + (size_t)3 * nW, wlo + (size_t)3 * nW,
        nullptr, nullptr, nullptr, nullptr, nullptr, nullptr, out, 1);
}

// round 17
// speedup vs baseline: 1.0174x; 1.0174x over previous
#include <cuda_runtime.h>
#include <cuda_bf16.h>
#include <cstdint>
#include <cstddef>

// Problem constants
#define BT      16384
#define DMODEL  1024
#define NH      8
#define DHD     128
#define CHUNKL  64
#define NCHUNK  128
#define NBATCH  2
#define NCHTOT  2048
#define QSCALE  0.08838834764831843f
#define RMSEPS  1e-5f

// Scratch buffers
__device__ float g_kv[(size_t)NCHTOT * 16384];
__device__ __nv_bfloat16 g_ahi[(size_t)BT * DMODEL];
__device__ __nv_bfloat16 g_alo[(size_t)BT * DMODEL];
__device__ __nv_bfloat16 g_whi[(size_t)4 * DMODEL * DMODEL];   // qkv + o_w
__device__ __nv_bfloat16 g_wlo[(size_t)4 * DMODEL * DMODEL];
__device__ __nv_bfloat16 g_qhi[(size_t)BT * DMODEL];
__device__ __nv_bfloat16 g_qlo[(size_t)BT * DMODEL];
__device__ __nv_bfloat16 g_khi[(size_t)BT * DMODEL];
__device__ __nv_bfloat16 g_klo[(size_t)BT * DMODEL];
__device__ __nv_bfloat16 g_fwhi[4 * DHD * DHD];
__device__ __nv_bfloat16 g_fwlo[4 * DHD * DHD];
__device__ __nv_bfloat16 g_qnh[(size_t)BT * DMODEL];
__device__ __nv_bfloat16 g_qnl[(size_t)BT * DMODEL];
__device__ __nv_bfloat16 g_kth[(size_t)BT * DMODEL];
__device__ __nv_bfloat16 g_ktl[(size_t)BT * DMODEL];
__device__ __nv_bfloat16 g_vth[(size_t)BT * DMODEL];
__device__ __nv_bfloat16 g_vtl[(size_t)BT * DMODEL];
__device__ __nv_bfloat16 g_sh[(size_t)NCHTOT * 16384];
__device__ __nv_bfloat16 g_sl[(size_t)NCHTOT * 16384];

#define SWZ(off) ((off) ^ (((off) >> 3) & 0x70))

__device__ __forceinline__ uint32_t smem_u32(const void* p) {
    uint32_t a;
    asm("{ .reg .u64 t; cvta.to.shared.u64 t, %1; cvt.u32.u64 %0, t; }" : "=r"(a) : "l"(p));
    return a;
}

__device__ __forceinline__ void ldsm_x4(uint32_t addr, uint32_t& r0, uint32_t& r1,
                                        uint32_t& r2, uint32_t& r3) {
    asm volatile("ldmatrix.sync.aligned.m8n8.x4.shared.b16 {%0,%1,%2,%3}, [%4];"
                 : "=r"(r0), "=r"(r1), "=r"(r2), "=r"(r3) : "r"(addr));
}

__device__ __forceinline__ void ldsm_x4_trans(uint32_t addr, uint32_t& r0, uint32_t& r1,
                                              uint32_t& r2, uint32_t& r3) {
    asm volatile("ldmatrix.sync.aligned.m8n8.x4.trans.shared.b16 {%0,%1,%2,%3}, [%4];"
                 : "=r"(r0), "=r"(r1), "=r"(r2), "=r"(r3) : "r"(addr));
}

__device__ __forceinline__ void mma_bf16(float* d, const uint32_t* a, const uint32_t* b) {
    asm volatile(
        "mma.sync.aligned.m16n8k16.row.col.f32.bf16.bf16.f32 "
        "{%0,%1,%2,%3}, {%4,%5,%6,%7}, {%8,%9}, {%0,%1,%2,%3};"
        : "+f"(d[0]), "+f"(d[1]), "+f"(d[2]), "+f"(d[3])
        : "r"(a[0]), "r"(a[1]), "r"(a[2]), "r"(a[3]), "r"(b[0]), "r"(b[1]));
}

__device__ __forceinline__ void cp_async16(uint32_t saddr, const void* gaddr) {
    asm volatile("cp.async.cg.shared.global [%0], [%1], 16;" :: "r"(saddr), "l"(gaddr));
}
#define CP_COMMIT() asm volatile("cp.async.commit_group;" ::: "memory")
#define CP_WAIT0()  asm volatile("cp.async.wait_group 0;" ::: "memory")
#define CP_WAIT1()  asm volatile("cp.async.wait_group 1;" ::: "memory")

__device__ __forceinline__ void split2(float a, float b, uint32_t& hi, uint32_t& lo) {
    __nv_bfloat16 ha = __float2bfloat16(a), hb = __float2bfloat16(b);
    __nv_bfloat16 la = __float2bfloat16(a - __bfloat162float(ha));
    __nv_bfloat16 lb = __float2bfloat16(b - __bfloat162float(hb));
    __nv_bfloat162 hp = __halves2bfloat162(ha, hb);
    __nv_bfloat162 lp = __halves2bfloat162(la, lb);
    hi = *(uint32_t*)&hp; lo = *(uint32_t*)&lp;
}

__device__ __forceinline__ void load_tile_async(uint32_t sdst, const void* gsrc,
                                                int slots, int tid) {
    for (int u = tid; u < slots; u += 256) {
        int row = u >> 3, cb = (u & 7) * 16;
        cp_async16(sdst + SWZ((uint32_t)(row * 128 + cb)),
                   (const char*)gsrc + (size_t)u * 16);
    }
}

// ---------------------------------------------------------------------------
// fp32 -> (hi, lo) bf16 split; 8 elems/thread (R15 measured-best).
// ---------------------------------------------------------------------------
__device__ __forceinline__ void split8(const float* x, __nv_bfloat16* hi,
                                       __nv_bfloat16* lo, int i) {
    float4 v0 = *(const float4*)(x + i);
    float4 v1 = *(const float4*)(x + i + 4);
    uint32_t h0, l0, h1, l1, h2, l2, h3, l3;
    split2(v0.x, v0.y, h0, l0);
    split2(v0.z, v0.w, h1, l1);
    split2(v1.x, v1.y, h2, l2);
    split2(v1.z, v1.w, h3, l3);
    *(uint4*)(hi + i) = make_uint4(h0, h1, h2, h3);
    *(uint4*)(lo + i) = make_uint4(l0, l1, l2, l3);
}

__global__ void split_f32(const float* __restrict__ x, __nv_bfloat16* __restrict__ hi,
                          __nv_bfloat16* __restrict__ lo, int n) {
    int i = (blockIdx.x * blockDim.x + threadIdx.x) * 8;
    if (i >= n) return;
    split8(x, hi, lo, i);
}

__global__ void split_f32_b4(const float* x0, const float* x1,
                             const float* x2, const float* x3,
                             __nv_bfloat16* __restrict__ hi,
                             __nv_bfloat16* __restrict__ lo, int n) {
    int which = blockIdx.y;
    const float* x = (which == 0) ? x0 : (which == 1) ? x1 : (which == 2) ? x2 : x3;
    int i = (blockIdx.x * blockDim.x + threadIdx.x) * 8;
    if (i >= n || x == nullptr) return;
    split8(x, hi + (size_t)which * n, lo + (size_t)which * n, i);
}

// ---------------------------------------------------------------------------
// HMMA GEMM (R12 champion): 64x128 CTA tile, BK=64, 2-stage cp.async,
// 256 threads / 8 warps, warp tile 32x32. 97KB smem -> 2 CTAs/SM.
// ---------------------------------------------------------------------------
#define GEMM_STAGE   49152
#define GEMM_SMEM_BYTES (2 * GEMM_STAGE + 1024)
#define VT_ROW 80

__device__ __forceinline__ void gemm_load_stage(uint32_t sdst,
                                                const char* Ah, const char* Al,
                                                const char* Bh, const char* Bl,
                                                size_t kbyte, int tid) {
#pragma unroll
    for (int l = 0; l < 2; l++) {
        int u = tid + 256 * l;
        int row = u >> 3;
        int cb = (u & 7) * 16;
        uint32_t dsw = SWZ((uint32_t)(row * 128 + cb));
        size_t off = (size_t)row * 2048 + kbyte + cb;
        cp_async16(sdst + dsw,        Ah + off);
        cp_async16(sdst + 8192 + dsw, Al + off);
    }
#pragma unroll
    for (int l = 0; l < 4; l++) {
        int u = tid + 256 * l;
        int row = u >> 3;
        int cb = (u & 7) * 16;
        uint32_t dsw = SWZ((uint32_t)(row * 128 + cb));
        size_t off = (size_t)row * 2048 + kbyte + cb;
        cp_async16(sdst + 16384 + dsw, Bh + off);
        cp_async16(sdst + 32768 + dsw, Bl + off);
    }
}

__global__ __launch_bounds__(256) void gemm_mma2(
    const __nv_bfloat16* __restrict__ Ahi, const __nv_bfloat16* __restrict__ Alo,
    const __nv_bfloat16* __restrict__ Whi, const __nv_bfloat16* __restrict__ Wlo,
    __nv_bfloat16* __restrict__ Qhi, __nv_bfloat16* __restrict__ Qlo,
    __nv_bfloat16* __restrict__ Khi, __nv_bfloat16* __restrict__ Klo,
    __nv_bfloat16* __restrict__ VTh, __nv_bfloat16* __restrict__ VTl,
    float* __restrict__ Cout, int mode) {
    extern __shared__ char dynraw[];
    char* smem = (char*)(((uintptr_t)dynraw + 1023) & ~(uintptr_t)1023);
    const uint32_t sbase = smem_u32(smem);

    const int tid = threadIdx.x;
    const int wid = tid >> 5;
    const int lane = tid & 31;
    const int n0 = blockIdx.x * 128;
    const int m0 = blockIdx.y * 64;
    const int wm = (wid & 1) * 32;
    const int wn = (wid >> 1) * 32;

    float acc[2][4][4];
#pragma unroll
    for (int i = 0; i < 2; i++)
#pragma unroll
        for (int j = 0; j < 4; j++)
#pragma unroll
            for (int r = 0; r < 4; r++) acc[i][j][r] = 0.f;

    const char* srcA_h = (const char*)(Ahi + (size_t)m0 * 1024);
    const char* srcA_l = (const char*)(Alo + (size_t)m0 * 1024);
    const char* srcB_h = (const char*)(Whi + (size_t)n0 * 1024);
    const char* srcB_l = (const char*)(Wlo + (size_t)n0 * 1024);

    const int mat = lane >> 3;
    const int mrow = lane & 7;

    gemm_load_stage(sbase, srcA_h, srcA_l, srcB_h, srcB_l, 0, tid);
    CP_COMMIT();

    for (int kt = 0; kt < 16; kt++) {
        CP_WAIT0();
        __syncthreads();

        if (kt + 1 < 16) {
            gemm_load_stage(sbase + (uint32_t)((kt + 1) & 1) * GEMM_STAGE,
                            srcA_h, srcA_l, srcB_h, srcB_l,
                            (size_t)(kt + 1) * 128, tid);
            CP_COMMIT();
        }
        const uint32_t scur = sbase + (uint32_t)(kt & 1) * GEMM_STAGE;
        const uint32_t sAh = scur;
        const uint32_t sAl = scur + 8192;
        const uint32_t sBh = scur + 16384;
        const uint32_t sBl = scur + 32768;

#pragma unroll
        for (int kc = 0; kc < 4; kc++) {
            const int kb0 = kc * 32;
            uint32_t ah[2][4], al[2][4];
#pragma unroll
            for (int i = 0; i < 2; i++) {
                int arow = wm + i * 16 + (mat & 1) * 8 + mrow;
                int akb = kb0 + (mat >> 1) * 16;
                uint32_t off = SWZ((uint32_t)(arow * 128 + akb));
                ldsm_x4(sAh + off, ah[i][0], ah[i][1], ah[i][2], ah[i][3]);
                ldsm_x4(sAl + off, al[i][0], al[i][1], al[i][2], al[i][3]);
            }
#pragma unroll
            for (int p = 0; p < 2; p++) {
                int brow = wn + p * 16 + (mat >> 1) * 8 + mrow;
                int bkb = kb0 + (mat & 1) * 16;
                uint32_t off = SWZ((uint32_t)(brow * 128 + bkb));
                uint32_t bh[4], bl[4];
                ldsm_x4(sBh + off, bh[0], bh[1], bh[2], bh[3]);
                ldsm_x4(sBl + off, bl[0], bl[1], bl[2], bl[3]);
#pragma unroll
                for (int i = 0; i < 2; i++) {
                    mma_bf16(acc[i][2 * p],     ah[i], &bh[0]);
                    mma_bf16(acc[i][2 * p],     al[i], &bh[0]);
                    mma_bf16(acc[i][2 * p],     ah[i], &bl[0]);
                    mma_bf16(acc[i][2 * p + 1], ah[i], &bh[2]);
                    mma_bf16(acc[i][2 * p + 1], al[i], &bh[2]);
                    mma_bf16(acc[i][2 * p + 1], ah[i], &bl[2]);
                }
            }
        }
    }

    const int crow = lane >> 2;
    const int ccol = (lane & 3) * 2;
    if (mode == 1) {
#pragma unroll
        for (int i = 0; i < 2; i++) {
            int m = m0 + wm + i * 16 + crow;
#pragma unroll
            for (int j = 0; j < 4; j++) {
                int n = n0 + wn + j * 8 + ccol;
                *(float2*)(Cout + (size_t)m * 1024 + n) = make_float2(acc[i][j][0], acc[i][j][1]);
                *(float2*)(Cout + (size_t)(m + 8) * 1024 + n) = make_float2(acc[i][j][2], acc[i][j][3]);
            }
        }
        return;
    }
    int buf = n0 >> 10;
    int ncol0 = n0 & 1023;
    if (buf == 2) {
        __syncthreads();
        __nv_bfloat16* sVh = (__nv_bfloat16*)smem;
        __nv_bfloat16* sVl = (__nv_bfloat16*)(smem + 128 * VT_ROW * 2);
#pragma unroll
        for (int i = 0; i < 2; i++) {
            int ma = wm + i * 16 + crow;
            int mb = ma + 8;
#pragma unroll
            for (int j = 0; j < 4; j++) {
                int n = wn + j * 8 + ccol;
                uint32_t hi, lo;
                split2(acc[i][j][0], acc[i][j][1], hi, lo);
                __nv_bfloat162 hp = *(__nv_bfloat162*)&hi;
                __nv_bfloat162 lp = *(__nv_bfloat162*)&lo;
                sVh[n * VT_ROW + ma] = hp.x; sVh[(n + 1) * VT_ROW + ma] = hp.y;
                sVl[n * VT_ROW + ma] = lp.x; sVl[(n + 1) * VT_ROW + ma] = lp.y;
                split2(acc[i][j][2], acc[i][j][3], hi, lo);
                hp = *(__nv_bfloat162*)&hi;
                lp = *(__nv_bfloat162*)&lo;
                sVh[n * VT_ROW + mb] = hp.x; sVh[(n + 1) * VT_ROW + mb] = hp.y;
                sVl[n * VT_ROW + mb] = lp.x; sVl[(n + 1) * VT_ROW + mb] = lp.y;
            }
        }
        __syncthreads();
        const size_t cid = ((size_t)(m0 >> 13) * 8 + (ncol0 >> 7)) * 128 + ((m0 >> 6) & 127);
#pragma unroll
        for (int l = 0; l < 4; l++) {
            int u = tid + 256 * l;
            int dv = u >> 3;
            int t0 = (u & 7) * 8;
            size_t g = (cid << 13) + (size_t)dv * 64 + t0;
            *(uint4*)(VTh + g) = *(uint4*)(sVh + dv * VT_ROW + t0);
            *(uint4*)(VTl + g) = *(uint4*)(sVl + dv * VT_ROW + t0);
        }
    } else {
        __nv_bfloat16* H = buf ? Khi : Qhi;
        __nv_bfloat16* L = buf ? Klo : Qlo;
#pragma unroll
        for (int i = 0; i < 2; i++) {
            int m = m0 + wm + i * 16 + crow;
#pragma unroll
            for (int j = 0; j < 4; j++) {
                int n = ncol0 + wn + j * 8 + ccol;
                uint32_t hi, lo;
                split2(acc[i][j][0], acc[i][j][1], hi, lo);
                *(uint32_t*)(H + (size_t)m * 1024 + n) = hi;
                *(uint32_t*)(L + (size_t)m * 1024 + n) = lo;
                split2(acc[i][j][2], acc[i][j][3], hi, lo);
                *(uint32_t*)(H + (size_t)(m + 8) * 1024 + n) = hi;
                *(uint32_t*)(L + (size_t)(m + 8) * 1024 + n) = lo;
            }
        }
    }
}

// ---------------------------------------------------------------------------
// Feature map via HMMA, 64-token CTA tile, 2 CTAs/SM. Merged q/k launch.
// q branch writes natural QN; k branch writes ONLY transposed KT.
// ---------------------------------------------------------------------------
#define FM_SMEM (98304 + 1024)

__global__ __launch_bounds__(256) void featmap_mma(
    const __nv_bfloat16* __restrict__ Qhi, const __nv_bfloat16* __restrict__ Qlo,
    const __nv_bfloat16* __restrict__ Khi, const __nv_bfloat16* __restrict__ Klo,
    const __nv_bfloat16* __restrict__ FWh, const __nv_bfloat16* __restrict__ FWl,
    const float* __restrict__ QB1, const float* __restrict__ QB2,
    const float* __restrict__ KB1, const float* __restrict__ KB2,
    __nv_bfloat16* __restrict__ QNh, __nv_bfloat16* __restrict__ QNl,
    __nv_bfloat16* __restrict__ OTh, __nv_bfloat16* __restrict__ OTl) {
    extern __shared__ char dynraw[];
    char* smem = (char*)(((uintptr_t)dynraw + 1023) & ~(uintptr_t)1023);
    const uint32_t sbase = smem_u32(smem);

    const int tid = threadIdx.x;
    const int wid = tid >> 5;
    const int lane = tid & 31;
    const int t0 = blockIdx.x * 64;
    const int h = blockIdx.y;
    const int isK = (int)(blockIdx.z >> 1);
    const int z = blockIdx.z & 1;
    const int wm = (wid & 1) * 32;
    const int wn = (wid >> 1) * 16;

    const int nF = DHD * DHD;
    const __nv_bfloat16* Xhi = isK ? Khi : Qhi;
    const __nv_bfloat16* Xlo = isK ? Klo : Qlo;
    const __nv_bfloat16* W1h = FWh + (isK ? 2 * nF : 0);
    const __nv_bfloat16* W1l = FWl + (isK ? 2 * nF : 0);
    const __nv_bfloat16* W2h = FWh + (isK ? 3 * nF : nF);
    const __nv_bfloat16* W2l = FWl + (isK ? 3 * nF : nF);
    const float* B1 = isK ? KB1 : QB1;
    const float* B2 = isK ? KB2 : QB2;
    const float scale = isK ? 1.0f : QSCALE;

    const __nv_bfloat16* wsel[4] = {W1h, W1l, W2h, W2l};

#pragma unroll
    for (int t = 0; t < 4; t++) {
        int half = t >> 1, hl = t & 1;
        const char* sp = (const char*)((hl ? Xlo : Xhi) +
                          (size_t)t0 * 1024 + h * 128 + half * 64);
#pragma unroll
        for (int l = 0; l < 2; l++) {
            int s = tid + 256 * l;
            int row = s >> 3, cb = (s & 7) * 16;
            cp_async16(sbase + t * 8192 + SWZ((uint32_t)(row * 128 + cb)),
                       sp + (size_t)row * 2048 + cb);
        }
    }
#pragma unroll
    for (int t = 0; t < 8; t++) {
        int half = t >> 2, wsub = (t >> 1) & 1, hl = t & 1;
        const char* sp = (const char*)wsel[wsub * 2 + hl] +
                         ((size_t)(z * 64) * 128 + half * 64) * 2;
#pragma unroll
        for (int l = 0; l < 2; l++) {
            int s = tid + 256 * l;
            int row = s >> 3, cb = (s & 7) * 16;
            cp_async16(sbase + 32768 + t * 8192 + SWZ((uint32_t)(row * 128 + cb)),
                       sp + (size_t)row * 256 + cb);
        }
    }
    CP_COMMIT();
    CP_WAIT0();
    __syncthreads();

    float acc1[2][2][4], acc2[2][2][4];
#pragma unroll
    for (int i = 0; i < 2; i++)
#pragma unroll
        for (int j = 0; j < 2; j++)
#pragma unroll
            for (int r = 0; r < 4; r++) { acc1[i][j][r] = 0.f; acc2[i][j][r] = 0.f; }

    const int mat = lane >> 3;
    const int mrow = lane & 7;

#pragma unroll
    for (int half = 0; half < 2; half++) {
        const uint32_t sXh = sbase + (half * 2 + 0) * 8192;
        const uint32_t sXl = sbase + (half * 2 + 1) * 8192;
        const uint32_t sW1h = sbase + 32768 + (half * 4 + 0) * 8192;
        const uint32_t sW1l = sbase + 32768 + (half * 4 + 1) * 8192;
        const uint32_t sW2h = sbase + 32768 + (half * 4 + 2) * 8192;
        const uint32_t sW2l = sbase + 32768 + (half * 4 + 3) * 8192;
#pragma unroll
        for (int kc = 0; kc < 4; kc++) {
            const int kb0 = kc * 32;
            uint32_t ah[2][4], al[2][4];
#pragma unroll
            for (int i = 0; i < 2; i++) {
                int arow = wm + i * 16 + (mat & 1) * 8 + mrow;
                int akb = kb0 + (mat >> 1) * 16;
                uint32_t off = SWZ((uint32_t)(arow * 128 + akb));
                ldsm_x4(sXh + off, ah[i][0], ah[i][1], ah[i][2], ah[i][3]);
                ldsm_x4(sXl + off, al[i][0], al[i][1], al[i][2], al[i][3]);
            }
            int brow = wn + (mat >> 1) * 8 + mrow;
            int bkb = kb0 + (mat & 1) * 16;
            uint32_t off = SWZ((uint32_t)(brow * 128 + bkb));
            uint32_t b1h[4], b1l[4], b2h[4], b2l[4];
            ldsm_x4(sW1h + off, b1h[0], b1h[1], b1h[2], b1h[3]);
            ldsm_x4(sW1l + off, b1l[0], b1l[1], b1l[2], b1l[3]);
            ldsm_x4(sW2h + off, b2h[0], b2h[1], b2h[2], b2h[3]);
            ldsm_x4(sW2l + off, b2l[0], b2l[1], b2l[2], b2l[3]);
#pragma unroll
            for (int i = 0; i < 2; i++) {
                mma_bf16(acc1[i][0], ah[i], &b1h[0]);
                mma_bf16(acc1[i][0], al[i], &b1h[0]);
                mma_bf16(acc1[i][0], ah[i], &b1l[0]);
                mma_bf16(acc1[i][1], ah[i], &b1h[2]);
                mma_bf16(acc1[i][1], al[i], &b1h[2]);
                mma_bf16(acc1[i][1], ah[i], &b1l[2]);
                mma_bf16(acc2[i][0], ah[i], &b2h[0]);
                mma_bf16(acc2[i][0], al[i], &b2h[0]);
                mma_bf16(acc2[i][0], ah[i], &b2l[0]);
                mma_bf16(acc2[i][1], ah[i], &b2h[2]);
                mma_bf16(acc2[i][1], al[i], &b2h[2]);
                mma_bf16(acc2[i][1], ah[i], &b2l[2]);
            }
        }
    }

    const int crow = lane >> 2;
    const int ccol = (lane & 3) * 2;
#pragma unroll
    for (int j = 0; j < 2; j++) {
        int d64 = wn + j * 8 + ccol;
        int nl = z * 64 + d64;
        float b1a = B1[nl], b1b = B1[nl + 1];
        float b2a = B2[nl], b2b = B2[nl + 1];
#pragma unroll
        for (int i = 0; i < 2; i++) {
#pragma unroll
            for (int rv = 0; rv < 2; rv++) {
                int m = t0 + wm + i * 16 + crow + rv * 8;
                float p0 = (acc1[i][j][rv * 2 + 0] + b1a) * (acc2[i][j][rv * 2 + 0] + b2a) * scale;
                float p1 = (acc1[i][j][rv * 2 + 1] + b1b) * (acc2[i][j][rv * 2 + 1] + b2b) * scale;
                uint32_t hi, lo;
                split2(p0, p1, hi, lo);
                int bb = m >> 13, nn = (m >> 6) & 127, cc = m & 63;
                size_t cidx = (size_t)(bb * 8 + h) * 128 + nn;
                if (isK) {
                    size_t addrT = (cidx << 13) + (size_t)nl * 64 + cc;
                    __nv_bfloat162 hp = *(__nv_bfloat162*)&hi;
                    __nv_bfloat162 lp = *(__nv_bfloat162*)&lo;
                    OTh[addrT] = hp.x; OTh[addrT + 64] = hp.y;
                    OTl[addrT] = lp.x; OTl[addrT + 64] = lp.y;
                } else {
                    size_t addrN = ((cidx * 2 + z) << 12) + cc * 64 + d64;
                    *(uint32_t*)(QNh + addrN) = hi;
                    *(uint32_t*)(QNl + addrN) = lo;
                }
            }
        }
    }
}

// ---------------------------------------------------------------------------
#define CKV_SMEM (65536 + 1024)

__global__ __launch_bounds__(256) void chunk_kv_mma(
    const __nv_bfloat16* __restrict__ VTh, const __nv_bfloat16* __restrict__ VTl,
    const __nv_bfloat16* __restrict__ KTh, const __nv_bfloat16* __restrict__ KTl,
    float* __restrict__ KV) {
    extern __shared__ char dynraw[];
    char* smem = (char*)(((uintptr_t)dynraw + 1023) & ~(uintptr_t)1023);
    const uint32_t sbase = smem_u32(smem);
    const int tid = threadIdx.x;
    const int wid = tid >> 5;
    const int lane = tid & 31;
    const size_t cid = blockIdx.x;
    const int wm = (wid & 3) * 32;
    const int wn = (wid >> 2) * 64;

    load_tile_async(sbase + 0,     VTh + (cid << 13), 1024, tid);
    load_tile_async(sbase + 16384, VTl + (cid << 13), 1024, tid);
    load_tile_async(sbase + 32768, KTh + (cid << 13), 1024, tid);
    load_tile_async(sbase + 49152, KTl + (cid << 13), 1024, tid);
    CP_COMMIT();
    CP_WAIT0();
    __syncthreads();

    float acc[2][8][4];
#pragma unroll
    for (int i = 0; i < 2; i++)
#pragma unroll
        for (int j = 0; j < 8; j++)
#pragma unroll
            for (int r = 0; r < 4; r++) acc[i][j][r] = 0.f;

    const int mat = lane >> 3;
    const int mrow = lane & 7;

#pragma unroll
    for (int kc = 0; kc < 4; kc++) {
        const int kb0 = kc * 32;
        uint32_t ah[2][4], al[2][4];
#pragma unroll
        for (int i = 0; i < 2; i++) {
            int arow = wm + i * 16 + (mat & 1) * 8 + mrow;
            int akb = kb0 + (mat >> 1) * 16;
            uint32_t off = SWZ((uint32_t)(arow * 128 + akb));
            ldsm_x4(sbase + off,         ah[i][0], ah[i][1], ah[i][2], ah[i][3]);
            ldsm_x4(sbase + 16384 + off, al[i][0], al[i][1], al[i][2], al[i][3]);
        }
#pragma unroll
        for (int p = 0; p < 4; p++) {
            int brow = wn + p * 16 + (mat >> 1) * 8 + mrow;
            int bkb = kb0 + (mat & 1) * 16;
            uint32_t off = SWZ((uint32_t)(brow * 128 + bkb));
            uint32_t bh[4], bl[4];
            ldsm_x4(sbase + 32768 + off, bh[0], bh[1], bh[2], bh[3]);
            ldsm_x4(sbase + 49152 + off, bl[0], bl[1], bl[2], bl[3]);
#pragma unroll
            for (int i = 0; i < 2; i++) {
                mma_bf16(acc[i][2 * p],     ah[i], &bh[0]);
                mma_bf16(acc[i][2 * p],     al[i], &bh[0]);
                mma_bf16(acc[i][2 * p],     ah[i], &bl[0]);
                mma_bf16(acc[i][2 * p + 1], ah[i], &bh[2]);
                mma_bf16(acc[i][2 * p + 1], al[i], &bh[2]);
                mma_bf16(acc[i][2 * p + 1], ah[i], &bl[2]);
            }
        }
    }

    const int crow = lane >> 2;
    const int ccol = (lane & 3) * 2;
    const int hk = wn >> 6;
#pragma unroll
    for (int i = 0; i < 2; i++) {
#pragma unroll
        for (int rv = 0; rv < 2; rv++) {
            int dv = wm + i * 16 + crow + rv * 8;
#pragma unroll
            for (int j = 0; j < 8; j++) {
                int dk64 = (wn & 63) + j * 8 + ccol;
                size_t addr = (cid << 14) + hk * 8192 + (size_t)dv * 64 + dk64;
                *(float2*)(KV + addr) = make_float2(acc[i][j][rv * 2], acc[i][j][rv * 2 + 1]);
            }
        }
    }
}

// ---------------------------------------------------------------------------
__global__ void cumsum_split(const float* __restrict__ KV,
                             __nv_bfloat16* __restrict__ Sh,
                             __nv_bfloat16* __restrict__ Sl) {
    int bh = blockIdx.x;
    size_t i = blockIdx.y * 256 + threadIdx.x;
    size_t base = ((size_t)bh * 128 << 14) + i;
    float acc = 0.f;
#pragma unroll 1
    for (int n = 0; n < NCHUNK; n += 4) {
        size_t i0 = base + ((size_t)n << 14);
        float v0 = KV[i0];
        float v1 = KV[i0 + (1u << 14)];
        float v2 = KV[i0 + (2u << 14)];
        float v3 = KV[i0 + (3u << 14)];
#pragma unroll
        for (int u = 0; u < 4; u++) {
            size_t idx = i0 + ((size_t)u << 14);
            __nv_bfloat16 h = __float2bfloat16(acc);
            Sh[idx] = h;
            Sl[idx] = __float2bfloat16(acc - __bfloat162float(h));
            acc += (u == 0) ? v0 : (u == 1) ? v1 : (u == 2) ? v2 : v3;
        }
    }
}

// ---------------------------------------------------------------------------
// chunk attention + fused RMSNorm + bf16 split. Step-1 B operand comes from
// the TRANSPOSED K tile (KT) via ldmatrix.trans -- no natural-K buffer needed.
// ---------------------------------------------------------------------------
#define CA_SMEM (180224 + 1024)

__global__ __launch_bounds__(256) void chunk_attn_mma(
    const __nv_bfloat16* __restrict__ QNh, const __nv_bfloat16* __restrict__ QNl,
    const __nv_bfloat16* __restrict__ KTh, const __nv_bfloat16* __restrict__ KTl,
    const __nv_bfloat16* __restrict__ VTh, const __nv_bfloat16* __restrict__ VTl,
    const __nv_bfloat16* __restrict__ Sh,  const __nv_bfloat16* __restrict__ Sl,
    const float* __restrict__ RW,
    __nv_bfloat16* __restrict__ Ohi, __nv_bfloat16* __restrict__ Olo) {
    extern __shared__ char dynraw[];
    char* smem = (char*)(((uintptr_t)dynraw + 1023) & ~(uintptr_t)1023);
    const uint32_t sQh = smem_u32(smem);
    const uint32_t sQl = sQh + 16384;
    const uint32_t sKh = sQh + 32768;   // KT tile: [dk 128][t 64*2B]
    const uint32_t sKl = sQh + 49152;
    const uint32_t sVh = sQh + 65536;
    const uint32_t sVl = sQh + 81920;
    const uint32_t sSh = sQh + 98304;
    const uint32_t sSl = sQh + 131072;
    const uint32_t sAh = sQh + 163840;
    const uint32_t sAl = sQh + 172032;
    __shared__ float ssbuf[64];

    const int tid = threadIdx.x;
    const int wid = tid >> 5;
    const int lane = tid & 31;
    const size_t cid = blockIdx.x;
    const int n = cid & 127;
    const int h = (cid >> 7) & 7;
    const int b = (int)(cid >> 10);

    load_tile_async(sQh, QNh + (cid << 13), 1024, tid);
    load_tile_async(sQl, QNl + (cid << 13), 1024, tid);
    load_tile_async(sKh, KTh + (cid << 13), 1024, tid);
    load_tile_async(sKl, KTl + (cid << 13), 1024, tid);
    CP_COMMIT();
    load_tile_async(sVh, VTh + (cid << 13), 1024, tid);
    load_tile_async(sVl, VTl + (cid << 13), 1024, tid);
    load_tile_async(sSh, Sh + (cid << 14), 2048, tid);
    load_tile_async(sSl, Sl + (cid << 14), 2048, tid);
    CP_COMMIT();
    CP_WAIT1();
    __syncthreads();

    const int mat = lane >> 3;
    const int mrow = lane & 7;
    const int crow = lane >> 2;
    const int ccol = (lane & 3) * 2;

    // ---- Step 1: A = Q K^T  (B fragments from KT via trans-ldsm)
    {
        const int wm1 = (wid & 1) * 32;
        const int wn1 = (wid >> 1) * 16;
        float acc[2][2][4];
#pragma unroll
        for (int i = 0; i < 2; i++)
#pragma unroll
            for (int j = 0; j < 2; j++)
#pragma unroll
                for (int r = 0; r < 4; r++) acc[i][j][r] = 0.f;

#pragma unroll
        for (int kc = 0; kc < 8; kc++) {
            int rbase = (kc >> 2) * 64;
            int kb0 = (kc & 3) * 32;
            uint32_t ah[2][4], al[2][4];
#pragma unroll
            for (int i = 0; i < 2; i++) {
                int arow = rbase + wm1 + i * 16 + (mat & 1) * 8 + mrow;
                int akb = kb0 + (mat >> 1) * 16;
                uint32_t off = SWZ((uint32_t)(arow * 128 + akb));
                ldsm_x4(sQh + off, ah[i][0], ah[i][1], ah[i][2], ah[i][3]);
                ldsm_x4(sQl + off, al[i][0], al[i][1], al[i][2], al[i][3]);
            }
            // B from KT: global dk = rbase + (kb0>>1) elems; matrix (k8 = mat&1, n8 = mat>>1)
            int dkrow = rbase + (kb0 >> 1) + (mat & 1) * 8 + mrow;
            int tbyte = (wn1 + (mat >> 1) * 8) * 2;
            uint32_t off = SWZ((uint32_t)(dkrow * 128 + tbyte));
            uint32_t bh[4], bl[4];
            ldsm_x4_trans(sKh + off, bh[0], bh[1], bh[2], bh[3]);
            ldsm_x4_trans(sKl + off, bl[0], bl[1], bl[2], bl[3]);
#pragma unroll
            for (int i = 0; i < 2; i++) {
                mma_bf16(acc[i][0], ah[i], &bh[0]);
                mma_bf16(acc[i][0], al[i], &bh[0]);
                mma_bf16(acc[i][0], ah[i], &bl[0]);
                mma_bf16(acc[i][1], ah[i], &bh[2]);
                mma_bf16(acc[i][1], al[i], &bh[2]);
                mma_bf16(acc[i][1], ah[i], &bl[2]);
            }
        }
#pragma unroll
        for (int i = 0; i < 2; i++) {
#pragma unroll
            for (int rv = 0; rv < 2; rv++) {
                int c = wm1 + i * 16 + crow + rv * 8;
#pragma unroll
                for (int j = 0; j < 2; j++) {
                    int s = wn1 + j * 8 + ccol;
                    float v0 = (s <= c)     ? acc[i][j][rv * 2 + 0] : 0.f;
                    float v1 = (s + 1 <= c) ? acc[i][j][rv * 2 + 1] : 0.f;
                    uint32_t hi, lo;
                    split2(v0, v1, hi, lo);
                    uint32_t off = SWZ((uint32_t)(c * 128 + s * 2));
                    asm volatile("st.shared.b32 [%0], %1;" :: "r"(sAh + off), "r"(hi));
                    asm volatile("st.shared.b32 [%0], %1;" :: "r"(sAl + off), "r"(lo));
                }
            }
        }
    }
    if (tid < 64) ssbuf[tid] = 0.f;
    CP_WAIT0();
    __syncthreads();

    // ---- Step 2: O = A V + Q S
    const int wm2 = (wid & 1) * 32;
    const int wn2 = (wid >> 1) * 32;
    float acc[2][4][4];
#pragma unroll
    for (int i = 0; i < 2; i++)
#pragma unroll
        for (int j = 0; j < 4; j++)
#pragma unroll
            for (int r = 0; r < 4; r++) acc[i][j][r] = 0.f;

#pragma unroll
    for (int kc = 0; kc < 4; kc++) {
        int kb0 = kc * 32;
        uint32_t ah[2][4], al[2][4];
#pragma unroll
        for (int i = 0; i < 2; i++) {
            int arow = wm2 + i * 16 + (mat & 1) * 8 + mrow;
            int akb = kb0 + (mat >> 1) * 16;
            uint32_t off = SWZ((uint32_t)(arow * 128 + akb));
            ldsm_x4(sAh + off, ah[i][0], ah[i][1], ah[i][2], ah[i][3]);
            ldsm_x4(sAl + off, al[i][0], al[i][1], al[i][2], al[i][3]);
        }
#pragma unroll
        for (int p = 0; p < 2; p++) {
            int brow = wn2 + p * 16 + (mat >> 1) * 8 + mrow;
            int bkb = kb0 + (mat & 1) * 16;
            uint32_t off = SWZ((uint32_t)(brow * 128 + bkb));
            uint32_t bh[4], bl[4];
            ldsm_x4(sVh + off, bh[0], bh[1], bh[2], bh[3]);
            ldsm_x4(sVl + off, bl[0], bl[1], bl[2], bl[3]);
#pragma unroll
            for (int i = 0; i < 2; i++) {
                mma_bf16(acc[i][2 * p],     ah[i], &bh[0]);
                mma_bf16(acc[i][2 * p],     al[i], &bh[0]);
                mma_bf16(acc[i][2 * p],     ah[i], &bl[0]);
                mma_bf16(acc[i][2 * p + 1], ah[i], &bh[2]);
                mma_bf16(acc[i][2 * p + 1], al[i], &bh[2]);
                mma_bf16(acc[i][2 * p + 1], ah[i], &bl[2]);
            }
        }
    }
#pragma unroll
    for (int kc = 0; kc < 8; kc++) {
        int qrbase = (kc >> 2) * 64;
        int srbase = (kc >> 2) * 128;
        int kb0 = (kc & 3) * 32;
        uint32_t ah[2][4], al[2][4];
#pragma unroll
        for (int i = 0; i < 2; i++) {
            int arow = qrbase + wm2 + i * 16 + (mat & 1) * 8 + mrow;
            int akb = kb0 + (mat >> 1) * 16;
            uint32_t off = SWZ((uint32_t)(arow * 128 + akb));
            ldsm_x4(sQh + off, ah[i][0], ah[i][1], ah[i][2], ah[i][3]);
            ldsm_x4(sQl + off, al[i][0], al[i][1], al[i][2], al[i][3]);
        }
#pragma unroll
        for (int p = 0; p < 2; p++) {
            int brow = srbase + wn2 + p * 16 + (mat >> 1) * 8 + mrow;
            int bkb = kb0 + (mat & 1) * 16;
            uint32_t off = SWZ((uint32_t)(brow * 128 + bkb));
            uint32_t bh[4], bl[4];
            ldsm_x4(sSh + off, bh[0], bh[1], bh[2], bh[3]);
            ldsm_x4(sSl + off, bl[0], bl[1], bl[2], bl[3]);
#pragma unroll
            for (int i = 0; i < 2; i++) {
                mma_bf16(acc[i][2 * p],     ah[i], &bh[0]);
                mma_bf16(acc[i][2 * p],     al[i], &bh[0]);
                mma_bf16(acc[i][2 * p],     ah[i], &bl[0]);
                mma_bf16(acc[i][2 * p + 1], ah[i], &bh[2]);
                mma_bf16(acc[i][2 * p + 1], al[i], &bh[2]);
                mma_bf16(acc[i][2 * p + 1], ah[i], &bl[2]);
            }
        }
    }

    // Fused RMSNorm
#pragma unroll
    for (int i = 0; i < 2; i++) {
#pragma unroll
        for (int rv = 0; rv < 2; rv++) {
            float ss = 0.f;
#pragma unroll
            for (int j = 0; j < 4; j++) {
                float v0 = acc[i][j][rv * 2], v1 = acc[i][j][rv * 2 + 1];
                ss += v0 * v0 + v1 * v1;
            }
            ss += __shfl_xor_sync(0xffffffffu, ss, 1);
            ss += __shfl_xor_sync(0xffffffffu, ss, 2);
            if ((lane & 3) == 0)
                atomicAdd(&ssbuf[wm2 + i * 16 + crow + rv * 8], ss);
        }
    }
    __syncthreads();

    const size_t tbase = (size_t)b * 8192 + (size_t)n * 64;
#pragma unroll
    for (int i = 0; i < 2; i++) {
#pragma unroll
        for (int rv = 0; rv < 2; rv++) {
            int tl = wm2 + i * 16 + crow + rv * 8;
            float r = rsqrtf(ssbuf[tl] * (1.0f / 128.0f) + RMSEPS);
            size_t t = tbase + tl;
#pragma unroll
            for (int j = 0; j < 4; j++) {
                int dv = wn2 + j * 8 + ccol;
                float2 w = *(const float2*)(RW + dv);
                uint32_t hi, lo;
                split2(acc[i][j][rv * 2] * r * w.x, acc[i][j][rv * 2 + 1] * r * w.y, hi, lo);
                *(uint32_t*)(Ohi + t * 1024 + h * 128 + dv) = hi;
                *(uint32_t*)(Olo + t * 1024 + h * 128 + dv) = lo;
            }
        }
    }
}

// ---------------------------------------------------------------------------
extern "C" void kernel_launch(void* const* d_in, const int* in_sizes, int n_in,
                              void* d_out, int out_size) {
    const float* hidden = (const float*)d_in[0];
    const float* q_w    = (const float*)d_in[2];
    const float* k_w    = (const float*)d_in[3];
    const float* v_w    = (const float*)d_in[4];
    const float* o_w    = (const float*)d_in[5];
    const float* fmq_w1 = (const float*)d_in[6];
    const float* fmq_b1 = (const float*)d_in[7];
    const float* fmq_w2 = (const float*)d_in[8];
    const float* fmq_b2 = (const float*)d_in[9];
    const float* fmk_w1 = (const float*)d_in[10];
    const float* fmk_b1 = (const float*)d_in[11];
    const float* fmk_w2 = (const float*)d_in[12];
    const float* fmk_b2 = (const float*)d_in[13];
    const float* rms_w  = (const float*)d_in[14];
    float* out = (float*)d_out;

    float* kv;
    __nv_bfloat16 *ahi, *alo, *whi, *wlo, *qhi, *qlo, *khi, *klo, *fwhi, *fwlo;
    __nv_bfloat16 *qnh, *qnl, *kth, *ktl, *vth, *vtl, *sh, *sl;
    cudaGetSymbolAddress((void**)&kv,   g_kv);
    cudaGetSymbolAddress((void**)&ahi,  g_ahi);
    cudaGetSymbolAddress((void**)&alo,  g_alo);
    cudaGetSymbolAddress((void**)&whi,  g_whi);
    cudaGetSymbolAddress((void**)&wlo,  g_wlo);
    cudaGetSymbolAddress((void**)&qhi,  g_qhi);
    cudaGetSymbolAddress((void**)&qlo,  g_qlo);
    cudaGetSymbolAddress((void**)&khi,  g_khi);
    cudaGetSymbolAddress((void**)&klo,  g_klo);
    cudaGetSymbolAddress((void**)&fwhi, g_fwhi);
    cudaGetSymbolAddress((void**)&fwlo, g_fwlo);
    cudaGetSymbolAddress((void**)&qnh,  g_qnh);
    cudaGetSymbolAddress((void**)&qnl,  g_qnl);
    cudaGetSymbolAddress((void**)&kth,  g_kth);
    cudaGetSymbolAddress((void**)&ktl,  g_ktl);
    cudaGetSymbolAddress((void**)&vth,  g_vth);
    cudaGetSymbolAddress((void**)&vtl,  g_vtl);
    cudaGetSymbolAddress((void**)&sh,   g_sh);
    cudaGetSymbolAddress((void**)&sl,   g_sl);

    cudaFuncSetAttribute(gemm_mma2, cudaFuncAttributeMaxDynamicSharedMemorySize, GEMM_SMEM_BYTES);
    cudaFuncSetAttribute(featmap_mma, cudaFuncAttributeMaxDynamicSharedMemorySize, FM_SMEM);
    cudaFuncSetAttribute(chunk_kv_mma, cudaFuncAttributeMaxDynamicSharedMemorySize, CKV_SMEM);
    cudaFuncSetAttribute(chunk_attn_mma, cudaFuncAttributeMaxDynamicSharedMemorySize, CA_SMEM);

    const int nA = BT * DMODEL;
    const int nW = DMODEL * DMODEL;
    const int nF = DHD * DHD;

    // Splits (8 elems/thread, R15 best): hidden; qkv+o weights; featmap weights
    split_f32<<<nA / 2048, 256>>>(hidden, ahi, alo, nA);
    split_f32_b4<<<dim3(nW / 2048, 4), 256>>>(q_w, k_w, v_w, o_w, whi, wlo, nW);
    split_f32_b4<<<dim3(nF / 2048, 4), 256>>>(fmq_w1, fmq_w2, fmk_w1, fmk_w2,
                                              fwhi, fwlo, nF);

    // QKV projection (64x128 tiles, 2 CTAs/SM)
    gemm_mma2<<<dim3(24, 256), 256, GEMM_SMEM_BYTES>>>(
        ahi, alo, whi, wlo, qhi, qlo, khi, klo, vth, vtl, nullptr, 0);

    // Feature maps: merged launch; q -> QN natural, k -> KT transposed only
    featmap_mma<<<dim3(BT / 64, NH, 4), 256, FM_SMEM>>>(
        qhi, qlo, khi, klo, fwhi, fwlo,
        fmq_b1, fmq_b2, fmk_b1, fmk_b2,
        qnh, qnl, kth, ktl);

    // Chunked linear attention (chunk_attn fuses RMSNorm + split -> ahi/alo)
    chunk_kv_mma<<<NCHTOT, 256, CKV_SMEM>>>(vth, vtl, kth, ktl, kv);
    cumsum_split<<<dim3(NBATCH * NH, 64), 256>>>(kv, sh, sl);
    chunk_attn_mma<<<NCHTOT, 256, CA_SMEM>>>(qnh, qnl, kth, ktl, vth, vtl, sh, sl,
                                             rms_w, ahi, alo);

    // Output projection (o_w weights at slot 3)
    gemm_mma2<<<dim3(8, 256), 256, GEMM_SMEM_BYTES>>>(
        ahi, alo, whi + (size_t)3 * nW, wlo + (size_t)3 * nW,
        nullptr, nullptr, nullptr, nullptr, nullptr, nullptr, out, 1);
}